// round 13
// baseline (speedup 1.0000x reference)
#include <cuda_runtime.h>
#include <cuda_bf16.h>
#include <math.h>

#define C_DIM 1000
#define ALPHA 0.01f
#define EPS_V 1e-15f
#define ROWS_PER_BLOCK 4          // 8 warps, 2 warps per row
#define MAX_PARTIALS 16384

// Scratch: transposed T_result in bf16 (2 MB) and per-block partial sums.
// g_partials zero-initialized; unused slots never written (safe to over-read).
__device__ __nv_bfloat16 g_Tt[C_DIM * C_DIM];
__device__ float g_partials[MAX_PARTIALS];

// ---------------------------------------------------------------------------
// Kernel 1: Tt[t][c] = bf16(T[c][t] + ALPHA*corr[c][t])  (R10 verbatim)
// ---------------------------------------------------------------------------
__global__ __launch_bounds__(256) void prep_T_kernel(const float* __restrict__ T,
                                                     const float* __restrict__ corr) {
    __shared__ float tile[32][34];
    const int t0 = blockIdx.x * 32;
    const int c0 = blockIdx.y * 32;
    const int tid = threadIdx.x;

    const int c_local = tid >> 3;
    const int c = c0 + c_local;
    const int f4 = (t0 >> 2) + (tid & 7);
    if (c < C_DIM && f4 < C_DIM / 4) {
        float4 a = __ldg(&reinterpret_cast<const float4*>(T    + (size_t)c * C_DIM)[f4]);
        float4 b = __ldg(&reinterpret_cast<const float4*>(corr + (size_t)c * C_DIM)[f4]);
        const int tl = (tid & 7) * 4;
        tile[tl + 0][c_local] = a.x + ALPHA * b.x;
        tile[tl + 1][c_local] = a.y + ALPHA * b.y;
        tile[tl + 2][c_local] = a.z + ALPHA * b.z;
        tile[tl + 3][c_local] = a.w + ALPHA * b.w;
    }
    __syncthreads();

#pragma unroll
    for (int it = 0; it < 2; it++) {
        const int tl = (tid >> 4) + it * 16;
        const int cp = tid & 15;
        const int t  = t0 + tl;
        const int cc = c0 + cp * 2;
        if (t < C_DIM && cc < C_DIM) {
            __nv_bfloat162 h = __floats2bfloat162_rn(tile[tl][cp * 2], tile[tl][cp * 2 + 1]);
            *reinterpret_cast<__nv_bfloat162*>(&g_Tt[(size_t)t * C_DIM + cc]) = h;
        }
    }
}

// ---------------------------------------------------------------------------
// Kernel 2: TWO warps per row (register diet -> occupancy).
// Chunk i4 covers classes [8*i4, 8*i4+8). Warp-half h owns chunks
// i4 = lane + 32*j + 64*h, j=0..1 (h=0: 0..63, h=1: 64..124, guarded).
// Per lane: 4 logits float4 + 2 Tt float4 live -> ~45 regs target.
// ---------------------------------------------------------------------------
__global__ __launch_bounds__(256) void row_loss_kernel(
    const float* __restrict__ logits,
    const int* __restrict__ target,
    int B) {
    const int tid   = threadIdx.x;
    const int warp  = tid >> 5;
    const int lane  = tid & 31;
    const int half  = warp & 1;          // which half of the row
    const int ri    = warp >> 1;         // row index within block (0..3)
    const int row   = blockIdx.x * ROWS_PER_BLOCK + ri;

    __shared__ float s_s[8];   // per-warp partial sums
    __shared__ float s_d[8];   // per-warp partial dots
    __shared__ float s_x[4];   // per-row x_t
    __shared__ float wsum[4];  // per-row contributions

    if (row < B) {
        const float4* r4 = reinterpret_cast<const float4*>(logits + (size_t)row * C_DIM);
        int t = target[row];
        t = (t < 0) ? 0 : ((t >= C_DIM) ? C_DIM - 1 : t);
        const float4* tt4 = reinterpret_cast<const float4*>(g_Tt + (size_t)t * C_DIM);

        // ---- loads: 2 chunks per lane (6 loads in flight) ----
        float4 v[4];
        float4 w4[2];
#pragma unroll
        for (int j = 0; j < 2; j++) {
            const int i4 = lane + 32 * j + 64 * half;
            if (i4 < 125) {
                v[2 * j]     = __ldcs(&r4[2 * i4]);
                v[2 * j + 1] = __ldcs(&r4[2 * i4 + 1]);
                w4[j]        = __ldg(&tt4[i4]);
            } else {
                v[2 * j]     = make_float4(-INFINITY, -INFINITY, -INFINITY, -INFINITY);
                v[2 * j + 1] = make_float4(-INFINITY, -INFINITY, -INFINITY, -INFINITY);
                w4[j]        = make_float4(0.f, 0.f, 0.f, 0.f);
            }
        }

        // ---- x_t extraction (owning half only; warp-uniform branch) ----
        const int f     = t >> 2;               // logits float4 index
        const int i4t   = f >> 1;               // chunk index 0..124
        const int ihalf = (i4t >= 64) ? 1 : 0;
        if (half == ihalf) {
            const int chunk = i4t - 64 * ihalf; // 0..63
            const int reg   = ((chunk >> 5) << 1) | (f & 1);
            const int srcl  = chunk & 31;
            const int comp  = t & 3;
            float4 vt;
            switch (reg) {
                case 0: vt = v[0]; break; case 1: vt = v[1]; break;
                case 2: vt = v[2]; break; default: vt = v[3]; break;
            }
            float cand = (comp == 0) ? vt.x : (comp == 1) ? vt.y : (comp == 2) ? vt.z : vt.w;
            float x_t = __shfl_sync(0xffffffffu, cand, srcl);
            if (lane == 0) s_x[ri] = x_t;
        }

        // ---- exp + sum + dot ----
        float s = 0.0f, d = 0.0f;
#pragma unroll
        for (int j = 0; j < 2; j++) {
            float4 a = v[2 * j];
            float4 b = v[2 * j + 1];
            a.x = __expf(a.x); a.y = __expf(a.y); a.z = __expf(a.z); a.w = __expf(a.w);
            b.x = __expf(b.x); b.y = __expf(b.y); b.z = __expf(b.z); b.w = __expf(b.w);
            s += (a.x + a.y + a.z + a.w) + (b.x + b.y + b.z + b.w);
            const __nv_bfloat162* h = reinterpret_cast<const __nv_bfloat162*>(&w4[j]);
            float2 p0 = __bfloat1622float2(h[0]);
            float2 p1 = __bfloat1622float2(h[1]);
            float2 p2 = __bfloat1622float2(h[2]);
            float2 p3 = __bfloat1622float2(h[3]);
            d += a.x * p0.x + a.y * p0.y + a.z * p1.x + a.w * p1.y
               + b.x * p2.x + b.y * p2.y + b.z * p3.x + b.w * p3.y;
        }

#pragma unroll
        for (int o = 16; o > 0; o >>= 1) {
            s += __shfl_xor_sync(0xffffffffu, s, o);
            d += __shfl_xor_sync(0xffffffffu, d, o);
        }
        if (lane == 0) { s_s[warp] = s; s_d[warp] = d; }
    }
    __syncthreads();

    // ---- per-row epilogue: one thread per row (warps with half==0) ----
    if ((warp & 1) == 0 && lane == 0) {
        float contrib = 0.0f;
        if (row < B) {
            const float s  = s_s[2 * ri] + s_s[2 * ri + 1];
            const float d  = s_d[2 * ri] + s_d[2 * ri + 1];
            const float xt = s_x[ri];
            float ce   = __logf(s) - xt;          // -log_softmax[t]
            float pro1 = __expf(xt) / s;          // p[t]
            float pro2 = d / s;                   // dot(p, Tt[t])
            contrib = (pro1 / (pro2 + EPS_V)) * ce;
        }
        wsum[ri] = contrib;
    }
    __syncthreads();

    if (tid == 0) {
        float s = 0.0f;
#pragma unroll
        for (int r = 0; r < ROWS_PER_BLOCK; r++) s += wsum[r];
        g_partials[blockIdx.x] = s;
    }
}

// ---------------------------------------------------------------------------
// Kernel 3: final reduction (R12 version — 1024 threads, MLP-16, fixed order).
// ---------------------------------------------------------------------------
__global__ __launch_bounds__(1024) void final_reduce_kernel(float* __restrict__ out,
                                                            float invB) {
    __shared__ float sh[1024];
    const int tid = threadIdx.x;
    float acc[MAX_PARTIALS / 1024];
#pragma unroll
    for (int k = 0; k < MAX_PARTIALS / 1024; k++)
        acc[k] = g_partials[tid + 1024 * k];
    float s = 0.0f;
#pragma unroll
    for (int k = 0; k < MAX_PARTIALS / 1024; k++) s += acc[k];
    sh[tid] = s;
    __syncthreads();
#pragma unroll
    for (int o = 512; o > 0; o >>= 1) {
        if (tid < o) sh[tid] += sh[tid + o];
        __syncthreads();
    }
    if (tid == 0) out[0] = sh[0] * invB;
}

// ---------------------------------------------------------------------------
extern "C" void kernel_launch(void* const* d_in, const int* in_sizes, int n_in,
                              void* d_out, int out_size) {
    const float* logits = (const float*)d_in[0];   // [B, C] fp32
    const float* corr   = (const float*)d_in[1];   // [C, C] fp32
    const int*   target = (const int*)d_in[2];     // [B] int32
    const float* T      = (const float*)d_in[3];   // [C, C] fp32

    const int B = in_sizes[2];

    dim3 grid((C_DIM + 31) / 32, (C_DIM + 31) / 32);   // 1024 blocks
    prep_T_kernel<<<grid, 256>>>(T, corr);

    int blocks = (B + ROWS_PER_BLOCK - 1) / ROWS_PER_BLOCK;   // 16384
    row_loss_kernel<<<blocks, 256>>>(logits, target, B);

    final_reduce_kernel<<<1, 1024>>>((float*)d_out, 1.0f / (float)B);
}

// round 14
// speedup vs baseline: 1.1311x; 1.1311x over previous
#include <cuda_runtime.h>
#include <cuda_bf16.h>
#include <math.h>

#define C_DIM 1000
#define ALPHA 0.01f
#define EPS_V 1e-15f
#define WARPS_PER_BLOCK 8
#define LOSS_BLOCKS 592           // 148 SMs x 4 blocks (persistent grid)
#define TOTAL_WARPS (LOSS_BLOCKS * WARPS_PER_BLOCK)
#define MAX_PARTIALS 16384

// Scratch: transposed T_result in bf16 (2 MB) and per-block partial sums.
// g_partials zero-initialized; slots >= LOSS_BLOCKS never written.
__device__ __nv_bfloat16 g_Tt[C_DIM * C_DIM];
__device__ float g_partials[MAX_PARTIALS];

// ---------------------------------------------------------------------------
// Kernel 1: Tt[t][c] = bf16(T[c][t] + ALPHA*corr[c][t])  (R10 verbatim)
// ---------------------------------------------------------------------------
__global__ __launch_bounds__(256) void prep_T_kernel(const float* __restrict__ T,
                                                     const float* __restrict__ corr) {
    __shared__ float tile[32][34];
    const int t0 = blockIdx.x * 32;
    const int c0 = blockIdx.y * 32;
    const int tid = threadIdx.x;

    const int c_local = tid >> 3;
    const int c = c0 + c_local;
    const int f4 = (t0 >> 2) + (tid & 7);
    if (c < C_DIM && f4 < C_DIM / 4) {
        float4 a = __ldg(&reinterpret_cast<const float4*>(T    + (size_t)c * C_DIM)[f4]);
        float4 b = __ldg(&reinterpret_cast<const float4*>(corr + (size_t)c * C_DIM)[f4]);
        const int tl = (tid & 7) * 4;
        tile[tl + 0][c_local] = a.x + ALPHA * b.x;
        tile[tl + 1][c_local] = a.y + ALPHA * b.y;
        tile[tl + 2][c_local] = a.z + ALPHA * b.z;
        tile[tl + 3][c_local] = a.w + ALPHA * b.w;
    }
    __syncthreads();

#pragma unroll
    for (int it = 0; it < 2; it++) {
        const int tl = (tid >> 4) + it * 16;
        const int cp = tid & 15;
        const int t  = t0 + tl;
        const int cc = c0 + cp * 2;
        if (t < C_DIM && cc < C_DIM) {
            __nv_bfloat162 h = __floats2bfloat162_rn(tile[tl][cp * 2], tile[tl][cp * 2 + 1]);
            *reinterpret_cast<__nv_bfloat162*>(&g_Tt[(size_t)t * C_DIM + cc]) = h;
        }
    }
}

// ---------------------------------------------------------------------------
// Kernel 2: PERSISTENT grid — one warp grid-strides over rows (R10 body
// unchanged inside the loop). Per iteration, consecutive warps read
// consecutive rows (sequential DRAM). Per-warp contrib accumulates in a
// register; one block reduction at the end.
// ---------------------------------------------------------------------------
__global__ __launch_bounds__(256) void row_loss_kernel(
    const float* __restrict__ logits,
    const int* __restrict__ target,
    int B) {
    const int warp  = threadIdx.x >> 5;
    const int lane  = threadIdx.x & 31;
    const int gwarp = blockIdx.x * WARPS_PER_BLOCK + warp;

    __shared__ float wsum[WARPS_PER_BLOCK];
    float acc = 0.0f;

    for (int row = gwarp; row < B; row += TOTAL_WARPS) {
        const float4* r4 = reinterpret_cast<const float4*>(logits + (size_t)row * C_DIM);
        int t = target[row];
        t = (t < 0) ? 0 : ((t >= C_DIM) ? C_DIM - 1 : t);
        const float4* tt4 = reinterpret_cast<const float4*>(g_Tt + (size_t)t * C_DIM);

        float4 v[8];
        float4 w4[4];
#pragma unroll
        for (int j = 0; j < 4; j++) {
            const int i4 = lane + 32 * j;
            if (i4 < 125) {
                v[2 * j]     = __ldcs(&r4[2 * i4]);
                v[2 * j + 1] = __ldcs(&r4[2 * i4 + 1]);
                w4[j]        = __ldg(&tt4[i4]);
            } else {
                v[2 * j]     = make_float4(-INFINITY, -INFINITY, -INFINITY, -INFINITY);
                v[2 * j + 1] = make_float4(-INFINITY, -INFINITY, -INFINITY, -INFINITY);
                w4[j]        = make_float4(0.f, 0.f, 0.f, 0.f);
            }
        }

        // ---- extract x_t (uniform shuffle) from raw logits ----
        const int f    = t >> 2;
        const int i4t  = f >> 1;
        const int reg  = ((i4t >> 5) << 1) | (f & 1);
        const int srcl = i4t & 31;
        const int comp = t & 3;
        float4 vt;
        switch (reg) {
            case 0: vt = v[0]; break; case 1: vt = v[1]; break;
            case 2: vt = v[2]; break; case 3: vt = v[3]; break;
            case 4: vt = v[4]; break; case 5: vt = v[5]; break;
            case 6: vt = v[6]; break; default: vt = v[7]; break;
        }
        float cand = (comp == 0) ? vt.x : (comp == 1) ? vt.y : (comp == 2) ? vt.z : vt.w;
        const float x_t = __shfl_sync(0xffffffffu, cand, srcl);

        // ---- exp + sum + dot (fused, no max subtraction) ----
        float s = 0.0f, d = 0.0f;
#pragma unroll
        for (int j = 0; j < 4; j++) {
            float4 a = v[2 * j];
            float4 b = v[2 * j + 1];
            a.x = __expf(a.x); a.y = __expf(a.y); a.z = __expf(a.z); a.w = __expf(a.w);
            b.x = __expf(b.x); b.y = __expf(b.y); b.z = __expf(b.z); b.w = __expf(b.w);
            s += (a.x + a.y + a.z + a.w) + (b.x + b.y + b.z + b.w);
            const __nv_bfloat162* h = reinterpret_cast<const __nv_bfloat162*>(&w4[j]);
            float2 p0 = __bfloat1622float2(h[0]);
            float2 p1 = __bfloat1622float2(h[1]);
            float2 p2 = __bfloat1622float2(h[2]);
            float2 p3 = __bfloat1622float2(h[3]);
            d += a.x * p0.x + a.y * p0.y + a.z * p1.x + a.w * p1.y
               + b.x * p2.x + b.y * p2.y + b.z * p3.x + b.w * p3.y;
        }

#pragma unroll
        for (int o = 16; o > 0; o >>= 1) {
            s += __shfl_xor_sync(0xffffffffu, s, o);
            d += __shfl_xor_sync(0xffffffffu, d, o);
        }

        if (lane == 0) {
            float lse  = __logf(s);
            float ce   = lse - x_t;                 // -log_softmax[t]
            float pro1 = __expf(x_t) / s;           // p[t]
            float pro2 = d / s;                     // dot(p, Tt[t])
            float beta = pro1 / (pro2 + EPS_V);
            acc += beta * ce;
        }
    }

    if (lane == 0) wsum[warp] = acc;
    __syncthreads();

    if (threadIdx.x == 0) {
        float s = 0.0f;
#pragma unroll
        for (int w = 0; w < WARPS_PER_BLOCK; w++) s += wsum[w];
        g_partials[blockIdx.x] = s;
    }
}

// ---------------------------------------------------------------------------
// Kernel 3: final reduction (1024 threads, MLP-16, fixed deterministic order).
// ---------------------------------------------------------------------------
__global__ __launch_bounds__(1024) void final_reduce_kernel(float* __restrict__ out,
                                                            float invB) {
    __shared__ float sh[1024];
    const int tid = threadIdx.x;
    float acc[MAX_PARTIALS / 1024];
#pragma unroll
    for (int k = 0; k < MAX_PARTIALS / 1024; k++)
        acc[k] = g_partials[tid + 1024 * k];
    float s = 0.0f;
#pragma unroll
    for (int k = 0; k < MAX_PARTIALS / 1024; k++) s += acc[k];
    sh[tid] = s;
    __syncthreads();
#pragma unroll
    for (int o = 512; o > 0; o >>= 1) {
        if (tid < o) sh[tid] += sh[tid + o];
        __syncthreads();
    }
    if (tid == 0) out[0] = sh[0] * invB;
}

// ---------------------------------------------------------------------------
extern "C" void kernel_launch(void* const* d_in, const int* in_sizes, int n_in,
                              void* d_out, int out_size) {
    const float* logits = (const float*)d_in[0];   // [B, C] fp32
    const float* corr   = (const float*)d_in[1];   // [C, C] fp32
    const int*   target = (const int*)d_in[2];     // [B] int32
    const float* T      = (const float*)d_in[3];   // [C, C] fp32

    const int B = in_sizes[2];

    dim3 grid((C_DIM + 31) / 32, (C_DIM + 31) / 32);   // 1024 blocks
    prep_T_kernel<<<grid, 256>>>(T, corr);

    row_loss_kernel<<<LOSS_BLOCKS, 32 * WARPS_PER_BLOCK>>>(logits, target, B);

    final_reduce_kernel<<<1, 1024>>>((float*)d_out, 1.0f / (float)B);
}

// round 15
// speedup vs baseline: 1.1574x; 1.0232x over previous
#include <cuda_runtime.h>
#include <cuda_bf16.h>
#include <cuda_fp8.h>
#include <math.h>

#define C_DIM 1000
#define ALPHA 0.01f
#define EPS_V 1e-15f
#define WARPS_PER_BLOCK 8
#define LOSS_BLOCKS 592           // 148 SMs x 4 blocks (persistent grid)
#define TOTAL_WARPS (LOSS_BLOCKS * WARPS_PER_BLOCK)
#define MAX_PARTIALS 16384
#define TT_SCALE 128.0f
#define TT_INV_SCALE 0.0078125f   // 1/128

// Scratch: transposed T_result in fp8 e4m3 (x128), stored as packed words.
// g_partials zero-initialized; slots >= LOSS_BLOCKS never written.
__device__ unsigned int g_Tt8[C_DIM * C_DIM / 4];   // 1 MB
__device__ float g_partials[MAX_PARTIALS];

// ---------------------------------------------------------------------------
// Kernel 1: Tt8[t][c] = e4m3((T[c][t] + ALPHA*corr[c][t]) * 128), 32x32 tiles.
// Load phase identical to R10; store phase packs 4 fp8 per uint32.
// ---------------------------------------------------------------------------
__global__ __launch_bounds__(256) void prep_T_kernel(const float* __restrict__ T,
                                                     const float* __restrict__ corr) {
    __shared__ float tile[32][34];
    const int t0 = blockIdx.x * 32;
    const int c0 = blockIdx.y * 32;
    const int tid = threadIdx.x;

    const int c_local = tid >> 3;
    const int c = c0 + c_local;
    const int f4 = (t0 >> 2) + (tid & 7);
    if (c < C_DIM && f4 < C_DIM / 4) {
        float4 a = __ldg(&reinterpret_cast<const float4*>(T    + (size_t)c * C_DIM)[f4]);
        float4 b = __ldg(&reinterpret_cast<const float4*>(corr + (size_t)c * C_DIM)[f4]);
        const int tl = (tid & 7) * 4;
        tile[tl + 0][c_local] = a.x + ALPHA * b.x;
        tile[tl + 1][c_local] = a.y + ALPHA * b.y;
        tile[tl + 2][c_local] = a.z + ALPHA * b.z;
        tile[tl + 3][c_local] = a.w + ALPHA * b.w;
    }
    __syncthreads();

    // ---- store: thread handles t-row tl = tid>>3, 4 consecutive c ----
    const int tl  = tid >> 3;            // 0..31
    const int c4  = tid & 7;             // 0..7 -> c_local 4*c4..4*c4+3
    const int t   = t0 + tl;
    const int cc  = c0 + 4 * c4;
    if (t < C_DIM && cc < C_DIM) {
        unsigned int b0 = __nv_cvt_float_to_fp8(tile[tl][4 * c4 + 0] * TT_SCALE, __NV_SATFINITE, __NV_E4M3);
        unsigned int b1 = __nv_cvt_float_to_fp8(tile[tl][4 * c4 + 1] * TT_SCALE, __NV_SATFINITE, __NV_E4M3);
        unsigned int b2 = __nv_cvt_float_to_fp8(tile[tl][4 * c4 + 2] * TT_SCALE, __NV_SATFINITE, __NV_E4M3);
        unsigned int b3 = __nv_cvt_float_to_fp8(tile[tl][4 * c4 + 3] * TT_SCALE, __NV_SATFINITE, __NV_E4M3);
        g_Tt8[(size_t)t * (C_DIM / 4) + (cc >> 2)] = b0 | (b1 << 8) | (b2 << 16) | (b3 << 24);
    }
}

// fp8x2 (e4m3) -> float2
__device__ __forceinline__ float2 f8x2_to_f2(unsigned int v) {
    __half2_raw hr = __nv_cvt_fp8x2_to_halfraw2((__nv_fp8x2_storage_t)v, __NV_E4M3);
    return __half22float2(*reinterpret_cast<__half2*>(&hr));
}

// ---------------------------------------------------------------------------
// Kernel 2: PERSISTENT grid, one warp per row per iteration (R14 structure).
// Tt row now fp8: chunk i4 loads 8 bytes (uint2) instead of 16.
// ---------------------------------------------------------------------------
__global__ __launch_bounds__(256) void row_loss_kernel(
    const float* __restrict__ logits,
    const int* __restrict__ target,
    int B) {
    const int warp  = threadIdx.x >> 5;
    const int lane  = threadIdx.x & 31;
    const int gwarp = blockIdx.x * WARPS_PER_BLOCK + warp;

    __shared__ float wsum[WARPS_PER_BLOCK];
    float acc = 0.0f;

    for (int row = gwarp; row < B; row += TOTAL_WARPS) {
        const float4* r4 = reinterpret_cast<const float4*>(logits + (size_t)row * C_DIM);
        int t = target[row];
        t = (t < 0) ? 0 : ((t >= C_DIM) ? C_DIM - 1 : t);
        // row base byte offset t*1000: 1000 % 8 == 0 -> uint2 aligned
        const uint2* tt8 = reinterpret_cast<const uint2*>(g_Tt8 + (size_t)t * (C_DIM / 4));

        float4 v[8];
        uint2  q[4];
#pragma unroll
        for (int j = 0; j < 4; j++) {
            const int i4 = lane + 32 * j;
            if (i4 < 125) {
                v[2 * j]     = __ldcs(&r4[2 * i4]);
                v[2 * j + 1] = __ldcs(&r4[2 * i4 + 1]);
                q[j]         = __ldg(&tt8[i4]);
            } else {
                v[2 * j]     = make_float4(-INFINITY, -INFINITY, -INFINITY, -INFINITY);
                v[2 * j + 1] = make_float4(-INFINITY, -INFINITY, -INFINITY, -INFINITY);
                q[j]         = make_uint2(0u, 0u);   // e4m3 0x00 == 0.0
            }
        }

        // ---- extract x_t (uniform shuffle) from raw logits ----
        const int f    = t >> 2;
        const int i4t  = f >> 1;
        const int reg  = ((i4t >> 5) << 1) | (f & 1);
        const int srcl = i4t & 31;
        const int comp = t & 3;
        float4 vt;
        switch (reg) {
            case 0: vt = v[0]; break; case 1: vt = v[1]; break;
            case 2: vt = v[2]; break; case 3: vt = v[3]; break;
            case 4: vt = v[4]; break; case 5: vt = v[5]; break;
            case 6: vt = v[6]; break; default: vt = v[7]; break;
        }
        float cand = (comp == 0) ? vt.x : (comp == 1) ? vt.y : (comp == 2) ? vt.z : vt.w;
        const float x_t = __shfl_sync(0xffffffffu, cand, srcl);

        // ---- exp + sum + dot (fp8 decode) ----
        float s = 0.0f, d = 0.0f;
#pragma unroll
        for (int j = 0; j < 4; j++) {
            float4 a = v[2 * j];
            float4 b = v[2 * j + 1];
            a.x = __expf(a.x); a.y = __expf(a.y); a.z = __expf(a.z); a.w = __expf(a.w);
            b.x = __expf(b.x); b.y = __expf(b.y); b.z = __expf(b.z); b.w = __expf(b.w);
            s += (a.x + a.y + a.z + a.w) + (b.x + b.y + b.z + b.w);
            float2 p0 = f8x2_to_f2(q[j].x & 0xFFFFu);
            float2 p1 = f8x2_to_f2(q[j].x >> 16);
            float2 p2 = f8x2_to_f2(q[j].y & 0xFFFFu);
            float2 p3 = f8x2_to_f2(q[j].y >> 16);
            d += a.x * p0.x + a.y * p0.y + a.z * p1.x + a.w * p1.y
               + b.x * p2.x + b.y * p2.y + b.z * p3.x + b.w * p3.y;
        }

#pragma unroll
        for (int o = 16; o > 0; o >>= 1) {
            s += __shfl_xor_sync(0xffffffffu, s, o);
            d += __shfl_xor_sync(0xffffffffu, d, o);
        }

        if (lane == 0) {
            float lse  = __logf(s);
            float ce   = lse - x_t;                       // -log_softmax[t]
            float pro1 = __expf(x_t) / s;                 // p[t]
            float pro2 = (d * TT_INV_SCALE) / s;          // dot(p, Tt[t])
            float beta = pro1 / (pro2 + EPS_V);
            acc += beta * ce;
        }
    }

    if (lane == 0) wsum[warp] = acc;
    __syncthreads();

    if (threadIdx.x == 0) {
        float s = 0.0f;
#pragma unroll
        for (int w = 0; w < WARPS_PER_BLOCK; w++) s += wsum[w];
        g_partials[blockIdx.x] = s;
    }
}

// ---------------------------------------------------------------------------
// Kernel 3: final reduction (1024 threads, MLP-16, fixed deterministic order).
// ---------------------------------------------------------------------------
__global__ __launch_bounds__(1024) void final_reduce_kernel(float* __restrict__ out,
                                                            float invB) {
    __shared__ float sh[1024];
    const int tid = threadIdx.x;
    float acc[MAX_PARTIALS / 1024];
#pragma unroll
    for (int k = 0; k < MAX_PARTIALS / 1024; k++)
        acc[k] = g_partials[tid + 1024 * k];
    float s = 0.0f;
#pragma unroll
    for (int k = 0; k < MAX_PARTIALS / 1024; k++) s += acc[k];
    sh[tid] = s;
    __syncthreads();
#pragma unroll
    for (int o = 512; o > 0; o >>= 1) {
        if (tid < o) sh[tid] += sh[tid + o];
        __syncthreads();
    }
    if (tid == 0) out[0] = sh[0] * invB;
}

// ---------------------------------------------------------------------------
extern "C" void kernel_launch(void* const* d_in, const int* in_sizes, int n_in,
                              void* d_out, int out_size) {
    const float* logits = (const float*)d_in[0];   // [B, C] fp32
    const float* corr   = (const float*)d_in[1];   // [C, C] fp32
    const int*   target = (const int*)d_in[2];     // [B] int32
    const float* T      = (const float*)d_in[3];   // [C, C] fp32

    const int B = in_sizes[2];

    dim3 grid((C_DIM + 31) / 32, (C_DIM + 31) / 32);   // 1024 blocks
    prep_T_kernel<<<grid, 256>>>(T, corr);

    row_loss_kernel<<<LOSS_BLOCKS, 32 * WARPS_PER_BLOCK>>>(logits, target, B);

    final_reduce_kernel<<<1, 1024>>>((float*)d_out, 1.0f / (float)B);
}